// round 14
// baseline (speedup 1.0000x reference)
#include <cuda_runtime.h>
#include <cstdint>

#define BB 16
#define TT 2048
#define FF 512
#define SPB 8      // segments per k_pool block
#define GR 16      // rows per k_gate block (32KB smem)
#define NMAX 1024  // counts = k+1 <= 1024 (strict minima are >=2 apart)

// Scratch (allocation-free rule: device globals)
__device__ float g_wt[BB * TT];      // gate weights
__device__ int   g_vlist[BB * TT];   // packed valley positions per batch
__device__ int   g_nv[BB];           // number of valleys k per batch

__device__ __forceinline__ uint32_t smem_u32(const void* p) {
    uint32_t a;
    asm("{ .reg .u64 t; cvta.to.shared.u64 t, %1; cvt.u32.u64 %0, t; }"
        : "=r"(a) : "l"(p));
    return a;
}

// ---------------------------------------------------------------------------
// Kernel 0: unconditional zeros for pooled rows [NMAX, TT) of every batch.
// No dependencies -> runs on a forked stream concurrent with k_gate.
// ---------------------------------------------------------------------------
__global__ void k_zero(float* __restrict__ out) {
    int b = blockIdx.y;
    float4* dst = (float4*)(out + ((size_t)b * TT + NMAX) * FF);
    float4 z = make_float4(0.f, 0.f, 0.f, 0.f);
    const int total = (TT - NMAX) * (FF / 4);       // 131072 float4 per batch
    for (int i = blockIdx.x * blockDim.x + threadIdx.x; i < total;
         i += gridDim.x * blockDim.x)
        __stcs(dst + i, z);
}

// ---------------------------------------------------------------------------
// Kernel 1 (champion, verbatim): wt = sigmoid(x·w + b). One-shot 32KB TMA.
// ---------------------------------------------------------------------------
__global__ void k_gate(const float* __restrict__ x,
                       const float* __restrict__ w,
                       const float* __restrict__ bias) {
    __shared__ alignas(16) float4 sx[GR * FF / 4];          // 32 KB
    __shared__ alignas(8)  unsigned long long mbar;

    int tid  = threadIdx.x;                                  // 256
    int lane = tid & 31;
    int wid  = tid >> 5;                                     // 8 warps

    const float4* wr = (const float4*)w;
    float4 c0 = wr[lane];
    float4 c1 = wr[lane + 32];
    float4 c2 = wr[lane + 64];
    float4 c3 = wr[lane + 96];
    float  bz = bias[0];

    uint32_t mb = smem_u32(&mbar);
    uint32_t ds = smem_u32(sx);
    const int BYTES = GR * FF * 4;                           // 32768

    if (tid == 0) {
        asm volatile("mbarrier.init.shared.b64 [%0], 1;" :: "r"(mb) : "memory");
    }
    __syncthreads();
    if (tid == 0) {
        const char* src = (const char*)x + (size_t)blockIdx.x * BYTES;
        asm volatile("mbarrier.arrive.expect_tx.shared.b64 _, [%0], %1;"
                     :: "r"(mb), "r"(BYTES) : "memory");
        asm volatile("cp.async.bulk.shared::cta.global.mbarrier::complete_tx::bytes "
                     "[%0], [%1], %2, [%3];"
                     :: "r"(ds), "l"(src), "r"(BYTES), "r"(mb) : "memory");
    }

    {
        uint32_t done;
        asm volatile(
            "{\n\t.reg .pred p;\n\t"
            "mbarrier.try_wait.parity.acquire.cta.shared::cta.b64 p, [%1], 0;\n\t"
            "selp.b32 %0, 1, 0, p;\n\t}"
            : "=r"(done) : "r"(mb) : "memory");
        if (!done) {
            asm volatile(
                "{\n\t.reg .pred P1;\n"
                "W%=:\n\t"
                "mbarrier.try_wait.parity.acquire.cta.shared::cta.b64 P1, [%0], 0, 0x989680;\n\t"
                "@P1 bra.uni D%=;\n\t"
                "bra.uni W%=;\n"
                "D%=:\n\t}"
                :: "r"(mb) : "memory");
        }
    }

    int r0 = wid * 2;
    const float4* row0 = sx + r0 * (FF / 4);
    const float4* row1 = row0 + (FF / 4);

    float s0 = 0.f, s1 = 0.f;
#pragma unroll
    for (int j = 0; j < 4; j++) {
        float4 cj = (j == 0) ? c0 : (j == 1) ? c1 : (j == 2) ? c2 : c3;
        float4 a0 = row0[lane + 32 * j];
        float4 a1 = row1[lane + 32 * j];
        s0 += a0.x * cj.x + a0.y * cj.y + a0.z * cj.z + a0.w * cj.w;
        s1 += a1.x * cj.x + a1.y * cj.y + a1.z * cj.z + a1.w * cj.w;
    }
#pragma unroll
    for (int o = 16; o; o >>= 1) {
        s0 += __shfl_down_sync(0xffffffffu, s0, o);
        s1 += __shfl_down_sync(0xffffffffu, s1, o);
    }
    if (lane == 0) {
        int r = blockIdx.x * GR + r0;
        float2 r2;
        r2.x = 1.f / (1.f + expf(-(s0 + bz)));
        r2.y = 1.f / (1.f + expf(-(s1 + bz)));
        *(float2*)(g_wt + r) = r2;
    }
}

// ---------------------------------------------------------------------------
// Kernel 2 (champion): per batch, strict local minima, left-packed. 1024 thr.
// ---------------------------------------------------------------------------
__global__ void k_valleys() {
    __shared__ float sw[TT];
    __shared__ int   wsum[32];

    int b    = blockIdx.x;
    int tid  = threadIdx.x;                // 1024 threads
    int lane = tid & 31;
    int wid  = tid >> 5;                   // 32 warps

    for (int t = tid; t < TT; t += 1024) sw[t] = g_wt[b * TT + t];
    __syncthreads();

    const int PER = TT / 1024;             // 2
    int base = tid * PER;
    unsigned char fl[PER];
    int c = 0;
#pragma unroll
    for (int j = 0; j < PER; j++) {
        int   t   = base + j;
        float wtt = sw[t];
        float bef = (t == 0)      ? 0.f : sw[t - 1];
        float aft = (t == TT - 1) ? 0.f : sw[t + 1];
        bool  v   = (wtt < bef) && (wtt < aft);
        fl[j] = v ? 1 : 0;
        c += v ? 1 : 0;
    }

    int incl = c;
#pragma unroll
    for (int o = 1; o < 32; o <<= 1) {
        int v = __shfl_up_sync(0xffffffffu, incl, o);
        if (lane >= o) incl += v;
    }
    if (lane == 31) wsum[wid] = incl;
    __syncthreads();
    if (tid == 0) {
        int run = 0;
#pragma unroll
        for (int j = 0; j < 32; j++) { int t = wsum[j]; wsum[j] = run; run += t; }
        g_nv[b] = run;
    }
    __syncthreads();

    int pos = wsum[wid] + incl - c;
#pragma unroll
    for (int j = 0; j < PER; j++) {
        if (fl[j]) g_vlist[b * TT + (pos++)] = base + j;
    }
}

// ---------------------------------------------------------------------------
// Kernel 3: streaming segment pooling over rows [0, NMAX) ONLY (rows >= NMAX
// are handled by k_zero). SPB segments per block, each x row read once,
// 2-row overlap carried in registers. Streaming stores.
// ---------------------------------------------------------------------------
__global__ void k_pool(const float* __restrict__ x,
                       float* __restrict__ out) {
    int b   = blockIdx.y;
    int j   = blockIdx.x;
    int tid = threadIdx.x;                 // 128
    int k = g_nv[b];
    int n = k + 1;                         // <= NMAX always
    int i0 = j * SPB;

    float4 z4 = make_float4(0.f, 0.f, 0.f, 0.f);
    for (int i = max(i0, n); i < i0 + SPB; i++)
        __stcs((float4*)(out + ((size_t)b * TT + i) * FF) + tid, z4);

    if (i0 < n) {
        int iEnd = min(i0 + SPB, n);
        const float4* xb = (const float4*)(x + (size_t)b * TT * FF);
        const float*  wb = g_wt + b * TT;
        const int*    vb = g_vlist + b * TT;

        float4 carry = z4;
        float  dcarry = 0.f;
        bool   have = false;

        for (int i = i0; i < iEnd; i++) {
            int S = (i == 0) ? 0 : vb[i - 1];
            int E = (i < k) ? min(vb[i] + 2, TT) : TT;

            float4 acc;
            float  den;
            int t;
            if (have) { acc = carry; den = dcarry; t = S + 2; }
            else      { acc = z4;    den = 0.f;    t = S;     }

            int bodyEnd = E - 2;
#pragma unroll 2
            for (; t < bodyEnd; t++) {
                float  wv = wb[t];
                float4 xv = xb[(size_t)t * (FF / 4) + tid];
                acc.x += wv * xv.x;  acc.y += wv * xv.y;
                acc.z += wv * xv.z;  acc.w += wv * xv.w;
                den += wv;
            }
            float4 c2 = z4;
            float  d2 = 0.f;
            for (; t < E; t++) {
                float  wv = wb[t];
                float4 xv = xb[(size_t)t * (FF / 4) + tid];
                acc.x += wv * xv.x;  acc.y += wv * xv.y;
                acc.z += wv * xv.z;  acc.w += wv * xv.w;
                den += wv;
                c2.x += wv * xv.x;  c2.y += wv * xv.y;
                c2.z += wv * xv.z;  c2.w += wv * xv.w;
                d2 += wv;
            }
            carry = c2; dcarry = d2; have = true;

            float inv = 1.f / fmaxf(den, 1e-6f);
            float4 r;
            r.x = acc.x * inv;  r.y = acc.y * inv;
            r.z = acc.z * inv;  r.w = acc.w * inv;
            __stcs((float4*)(out + ((size_t)b * TT + i) * FF) + tid, r);
        }
    }
}

// ---------------------------------------------------------------------------
// Kernel 4: new_mask over all [BB, TT] (nl can exceed NMAX).
// ---------------------------------------------------------------------------
__global__ void k_mask(const int* __restrict__ seq_len,
                       float* __restrict__ out) {
    __shared__ int s_mc;
    int tid = threadIdx.x;                 // 256
    if (tid == 0) {
        int mc = 0;
#pragma unroll
        for (int bb = 0; bb < BB; bb++) {
            int c = g_nv[bb] + 1;
            if (c > mc) mc = c;
        }
        s_mc = mc;
    }
    __syncthreads();
    int g = blockIdx.x * 256 + tid;        // grid = BB*TT/256 = 128
    int b = g / TT;
    int i = g % TT;
    int len  = min(seq_len[b], TT);
    int len0 = min(seq_len[0], TT);
    int nl   = (int)((float)len / (float)len0 * (float)s_mc);
    float* m = out + (size_t)BB * TT * FF;
    __stcs(&m[g], (i < nl) ? 1.f : 0.f);
}

// ---------------------------------------------------------------------------
extern "C" void kernel_launch(void* const* d_in, const int* in_sizes, int n_in,
                              void* d_out, int out_size) {
    const float* x    = (const float*)d_in[0];   // [B,T,F] f32
    const float* w    = (const float*)d_in[1];   // [F,1]  f32
    const float* bias = (const float*)d_in[2];   // [1]    f32
    const int*   seq  = (const int*)d_in[3];     // [B]    i32
    float* out = (float*)d_out;

    int write_mask = (out_size >= BB * TT * FF + BB * TT) ? 1 : 0;

    dim3 zero_grid(64, BB);                         // 1024 blocks x 256 thr
    dim3 pool_grid(NMAX / SPB, BB);                 // 128 x 16

    cudaStream_t s2 = 0;
    cudaEvent_t evZ = 0;
    bool forked =
        (cudaStreamCreateWithFlags(&s2, cudaStreamNonBlocking) == cudaSuccess) &&
        (cudaEventCreateWithFlags(&evZ, cudaEventDisableTiming) == cudaSuccess);

    if (forked) {
        // fork must branch FROM the capture-origin stream: record an event on
        // the main stream first, make s2 wait on it, then run k_zero there.
        cudaEvent_t evF = 0;
        if (cudaEventCreateWithFlags(&evF, cudaEventDisableTiming) == cudaSuccess) {
            cudaEventRecord(evF, 0);
            cudaStreamWaitEvent(s2, evF, 0);
        }
        k_zero<<<zero_grid, 256, 0, s2>>>(out);      // rows [NMAX,TT): pure writes
        cudaEventRecord(evZ, s2);

        k_gate<<<(BB * TT) / GR, 256>>>(x, w, bias); // overlaps k_zero
        k_valleys<<<BB, 1024>>>();
        k_pool<<<pool_grid, 128>>>(x, out);          // rows [0,NMAX) only
        cudaStreamWaitEvent(0, evZ, 0);              // join fork
        if (write_mask)
            k_mask<<<(BB * TT) / 256, 256>>>(seq, out);
        // handles intentionally not destroyed (capture-referenced)
    } else {
        k_zero<<<zero_grid, 256>>>(out);
        k_gate<<<(BB * TT) / GR, 256>>>(x, w, bias);
        k_valleys<<<BB, 1024>>>();
        k_pool<<<pool_grid, 128>>>(x, out);
        if (write_mask)
            k_mask<<<(BB * TT) / 256, 256>>>(seq, out);
    }
}

// round 15
// speedup vs baseline: 1.1791x; 1.1791x over previous
#include <cuda_runtime.h>
#include <cstdint>

#define BB 16
#define TT 2048
#define FF 512
#define SPB 8      // segments per k_pool block
#define GR 16      // rows per k_gate block (32KB smem)

// Scratch (allocation-free rule: device globals)
__device__ float g_wt[BB * TT];      // gate weights
__device__ int   g_vlist[BB * TT];   // packed valley positions per batch
__device__ int   g_nv[BB];           // number of valleys k per batch

__device__ __forceinline__ uint32_t smem_u32(const void* p) {
    uint32_t a;
    asm("{ .reg .u64 t; cvta.to.shared.u64 t, %1; cvt.u32.u64 %0, t; }"
        : "=r"(a) : "l"(p));
    return a;
}

// ---------------------------------------------------------------------------
// Kernel 1 (champion, verbatim): wt = sigmoid(x·w + b). One-shot 32KB TMA
// into smem; each warp dots 2 rows from smem against register-held w.
// ---------------------------------------------------------------------------
__global__ void k_gate(const float* __restrict__ x,
                       const float* __restrict__ w,
                       const float* __restrict__ bias) {
    __shared__ alignas(16) float4 sx[GR * FF / 4];          // 32 KB
    __shared__ alignas(8)  unsigned long long mbar;

    int tid  = threadIdx.x;                                  // 256
    int lane = tid & 31;
    int wid  = tid >> 5;                                     // 8 warps

    const float4* wr = (const float4*)w;
    float4 c0 = wr[lane];
    float4 c1 = wr[lane + 32];
    float4 c2 = wr[lane + 64];
    float4 c3 = wr[lane + 96];
    float  bz = bias[0];

    uint32_t mb = smem_u32(&mbar);
    uint32_t ds = smem_u32(sx);
    const int BYTES = GR * FF * 4;                           // 32768

    if (tid == 0) {
        asm volatile("mbarrier.init.shared.b64 [%0], 1;" :: "r"(mb) : "memory");
    }
    __syncthreads();
    if (tid == 0) {
        const char* src = (const char*)x + (size_t)blockIdx.x * BYTES;
        asm volatile("mbarrier.arrive.expect_tx.shared.b64 _, [%0], %1;"
                     :: "r"(mb), "r"(BYTES) : "memory");
        asm volatile("cp.async.bulk.shared::cta.global.mbarrier::complete_tx::bytes "
                     "[%0], [%1], %2, [%3];"
                     :: "r"(ds), "l"(src), "r"(BYTES), "r"(mb) : "memory");
    }

    {
        uint32_t done;
        asm volatile(
            "{\n\t.reg .pred p;\n\t"
            "mbarrier.try_wait.parity.acquire.cta.shared::cta.b64 p, [%1], 0;\n\t"
            "selp.b32 %0, 1, 0, p;\n\t}"
            : "=r"(done) : "r"(mb) : "memory");
        if (!done) {
            asm volatile(
                "{\n\t.reg .pred P1;\n"
                "W%=:\n\t"
                "mbarrier.try_wait.parity.acquire.cta.shared::cta.b64 P1, [%0], 0, 0x989680;\n\t"
                "@P1 bra.uni D%=;\n\t"
                "bra.uni W%=;\n"
                "D%=:\n\t}"
                :: "r"(mb) : "memory");
        }
    }

    int r0 = wid * 2;
    const float4* row0 = sx + r0 * (FF / 4);
    const float4* row1 = row0 + (FF / 4);

    float s0 = 0.f, s1 = 0.f;
#pragma unroll
    for (int j = 0; j < 4; j++) {
        float4 cj = (j == 0) ? c0 : (j == 1) ? c1 : (j == 2) ? c2 : c3;
        float4 a0 = row0[lane + 32 * j];
        float4 a1 = row1[lane + 32 * j];
        s0 += a0.x * cj.x + a0.y * cj.y + a0.z * cj.z + a0.w * cj.w;
        s1 += a1.x * cj.x + a1.y * cj.y + a1.z * cj.z + a1.w * cj.w;
    }
#pragma unroll
    for (int o = 16; o; o >>= 1) {
        s0 += __shfl_down_sync(0xffffffffu, s0, o);
        s1 += __shfl_down_sync(0xffffffffu, s1, o);
    }
    if (lane == 0) {
        int r = blockIdx.x * GR + r0;
        float2 r2;
        r2.x = 1.f / (1.f + expf(-(s0 + bz)));
        r2.y = 1.f / (1.f + expf(-(s1 + bz)));
        *(float2*)(g_wt + r) = r2;
    }
}

// ---------------------------------------------------------------------------
// Kernel 2 (champion): per batch, strict local minima, left-packed. 1024 thr.
// ---------------------------------------------------------------------------
__global__ void k_valleys() {
    __shared__ float sw[TT];
    __shared__ int   wsum[32];

    int b    = blockIdx.x;
    int tid  = threadIdx.x;                // 1024 threads
    int lane = tid & 31;
    int wid  = tid >> 5;                   // 32 warps

    for (int t = tid; t < TT; t += 1024) sw[t] = g_wt[b * TT + t];
    __syncthreads();

    const int PER = TT / 1024;             // 2
    int base = tid * PER;
    unsigned char fl[PER];
    int c = 0;
#pragma unroll
    for (int j = 0; j < PER; j++) {
        int   t   = base + j;
        float wtt = sw[t];
        float bef = (t == 0)      ? 0.f : sw[t - 1];
        float aft = (t == TT - 1) ? 0.f : sw[t + 1];
        bool  v   = (wtt < bef) && (wtt < aft);
        fl[j] = v ? 1 : 0;
        c += v ? 1 : 0;
    }

    int incl = c;
#pragma unroll
    for (int o = 1; o < 32; o <<= 1) {
        int v = __shfl_up_sync(0xffffffffu, incl, o);
        if (lane >= o) incl += v;
    }
    if (lane == 31) wsum[wid] = incl;
    __syncthreads();
    if (tid == 0) {
        int run = 0;
#pragma unroll
        for (int j = 0; j < 32; j++) { int t = wsum[j]; wsum[j] = run; run += t; }
        g_nv[b] = run;
    }
    __syncthreads();

    int pos = wsum[wid] + incl - c;
#pragma unroll
    for (int j = 0; j < PER; j++) {
        if (fl[j]) g_vlist[b * TT + (pos++)] = base + j;
    }
}

// ---------------------------------------------------------------------------
// Kernel 3 (champion structure): streaming segment pooling; SPB segments per
// block, each x row read once, 2-row overlap carried in registers (ascending
// sum order preserved). Streaming stores keep x resident in L2. Mask slice
// written FIRST (dependency-free) so its store drains during segment work.
// ---------------------------------------------------------------------------
__global__ void k_pool(const float* __restrict__ x,
                       const int* __restrict__ seq_len,
                       float* __restrict__ out,
                       int write_mask) {
    int b   = blockIdx.y;
    int j   = blockIdx.x;
    int tid = threadIdx.x;                 // 128
    int i0 = j * SPB;

    // mask slice first — no dependency on segment sums
    if (write_mask && tid < SPB) {
        int i = i0 + tid;
        int mc = 0;
#pragma unroll
        for (int bb = 0; bb < BB; bb++) {
            int c = g_nv[bb] + 1;
            if (c > mc) mc = c;
        }
        int len  = min(seq_len[b], TT);
        int len0 = min(seq_len[0], TT);
        int nl   = (int)((float)len / (float)len0 * (float)mc);
        float* m = out + (size_t)BB * TT * FF;
        __stcs(&m[(size_t)b * TT + i], (i < nl) ? 1.f : 0.f);
    }

    int k = g_nv[b];
    int n = k + 1;

    float4 z4 = make_float4(0.f, 0.f, 0.f, 0.f);
    for (int i = max(i0, n); i < i0 + SPB; i++)
        __stcs((float4*)(out + ((size_t)b * TT + i) * FF) + tid, z4);

    if (i0 < n) {
        int iEnd = min(i0 + SPB, n);
        const float4* xb = (const float4*)(x + (size_t)b * TT * FF);
        const float*  wb = g_wt + b * TT;
        const int*    vb = g_vlist + b * TT;

        float4 carry = z4;
        float  dcarry = 0.f;
        bool   have = false;

        for (int i = i0; i < iEnd; i++) {
            int S = (i == 0) ? 0 : vb[i - 1];
            int E = (i < k) ? min(vb[i] + 2, TT) : TT;

            float4 acc;
            float  den;
            int t;
            if (have) { acc = carry; den = dcarry; t = S + 2; }
            else      { acc = z4;    den = 0.f;    t = S;     }

            int bodyEnd = E - 2;
#pragma unroll 4
            for (; t < bodyEnd; t++) {
                float  wv = wb[t];
                float4 xv = xb[(size_t)t * (FF / 4) + tid];
                acc.x += wv * xv.x;  acc.y += wv * xv.y;
                acc.z += wv * xv.z;  acc.w += wv * xv.w;
                den += wv;
            }
            float4 c2 = z4;
            float  d2 = 0.f;
            for (; t < E; t++) {
                float  wv = wb[t];
                float4 xv = xb[(size_t)t * (FF / 4) + tid];
                acc.x += wv * xv.x;  acc.y += wv * xv.y;
                acc.z += wv * xv.z;  acc.w += wv * xv.w;
                den += wv;
                c2.x += wv * xv.x;  c2.y += wv * xv.y;
                c2.z += wv * xv.z;  c2.w += wv * xv.w;
                d2 += wv;
            }
            carry = c2; dcarry = d2; have = true;

            float inv = 1.f / fmaxf(den, 1e-6f);
            float4 r;
            r.x = acc.x * inv;  r.y = acc.y * inv;
            r.z = acc.z * inv;  r.w = acc.w * inv;
            __stcs((float4*)(out + ((size_t)b * TT + i) * FF) + tid, r);
        }
    }
}

// ---------------------------------------------------------------------------
extern "C" void kernel_launch(void* const* d_in, const int* in_sizes, int n_in,
                              void* d_out, int out_size) {
    const float* x    = (const float*)d_in[0];   // [B,T,F] f32
    const float* w    = (const float*)d_in[1];   // [F,1]  f32
    const float* bias = (const float*)d_in[2];   // [1]    f32
    const int*   seq  = (const int*)d_in[3];     // [B]    i32
    float* out = (float*)d_out;

    int write_mask = (out_size >= BB * TT * FF + BB * TT) ? 1 : 0;

    k_gate<<<(BB * TT) / GR, 256>>>(x, w, bias);   // 2048 blocks, TMA
    k_valleys<<<BB, 1024>>>();
    dim3 grid(TT / SPB, BB);                       // 256 x 16 blocks
    k_pool<<<grid, 128>>>(x, seq, out, write_mask);
}

// round 16
// speedup vs baseline: 1.1903x; 1.0095x over previous
#include <cuda_runtime.h>
#include <cstdint>

#define BB 16
#define TT 2048
#define FF 512
#define SPB 8      // segments per k_pool block
#define GR 16      // rows per k_gate block (32KB smem)

// Scratch (allocation-free rule: device globals)
__device__ float g_wt[BB * TT];      // gate weights
__device__ int   g_vlist[BB * TT];   // packed valley positions per batch
__device__ int   g_nv[BB];           // number of valleys k per batch

__device__ __forceinline__ uint32_t smem_u32(const void* p) {
    uint32_t a;
    asm("{ .reg .u64 t; cvta.to.shared.u64 t, %1; cvt.u32.u64 %0, t; }"
        : "=r"(a) : "l"(p));
    return a;
}

// ---------------------------------------------------------------------------
// Kernel 1: wt = sigmoid(x·w + b). ONE cp.async.bulk (TMA) copies 16 rows
// (32KB) into smem; each warp dots 2 rows from smem against register-held w.
// ---------------------------------------------------------------------------
__global__ void k_gate(const float* __restrict__ x,
                       const float* __restrict__ w,
                       const float* __restrict__ bias) {
    __shared__ alignas(16) float4 sx[GR * FF / 4];          // 32 KB
    __shared__ alignas(8)  unsigned long long mbar;

    int tid  = threadIdx.x;                                  // 256
    int lane = tid & 31;
    int wid  = tid >> 5;                                     // 8 warps

    const float4* wr = (const float4*)w;
    float4 c0 = wr[lane];
    float4 c1 = wr[lane + 32];
    float4 c2 = wr[lane + 64];
    float4 c3 = wr[lane + 96];
    float  bz = bias[0];

    uint32_t mb = smem_u32(&mbar);
    uint32_t ds = smem_u32(sx);
    const int BYTES = GR * FF * 4;                           // 32768

    if (tid == 0) {
        asm volatile("mbarrier.init.shared.b64 [%0], 1;" :: "r"(mb) : "memory");
    }
    __syncthreads();
    if (tid == 0) {
        const char* src = (const char*)x + (size_t)blockIdx.x * BYTES;
        asm volatile("mbarrier.arrive.expect_tx.shared.b64 _, [%0], %1;"
                     :: "r"(mb), "r"(BYTES) : "memory");
        asm volatile("cp.async.bulk.shared::cta.global.mbarrier::complete_tx::bytes "
                     "[%0], [%1], %2, [%3];"
                     :: "r"(ds), "l"(src), "r"(BYTES), "r"(mb) : "memory");
    }

    {
        uint32_t done;
        asm volatile(
            "{\n\t.reg .pred p;\n\t"
            "mbarrier.try_wait.parity.acquire.cta.shared::cta.b64 p, [%1], 0;\n\t"
            "selp.b32 %0, 1, 0, p;\n\t}"
            : "=r"(done) : "r"(mb) : "memory");
        if (!done) {
            asm volatile(
                "{\n\t.reg .pred P1;\n"
                "W%=:\n\t"
                "mbarrier.try_wait.parity.acquire.cta.shared::cta.b64 P1, [%0], 0, 0x989680;\n\t"
                "@P1 bra.uni D%=;\n\t"
                "bra.uni W%=;\n"
                "D%=:\n\t}"
                :: "r"(mb) : "memory");
        }
    }

    int r0 = wid * 2;
    const float4* row0 = sx + r0 * (FF / 4);
    const float4* row1 = row0 + (FF / 4);

    float s0 = 0.f, s1 = 0.f;
#pragma unroll
    for (int j = 0; j < 4; j++) {
        float4 cj = (j == 0) ? c0 : (j == 1) ? c1 : (j == 2) ? c2 : c3;
        float4 a0 = row0[lane + 32 * j];
        float4 a1 = row1[lane + 32 * j];
        s0 += a0.x * cj.x + a0.y * cj.y + a0.z * cj.z + a0.w * cj.w;
        s1 += a1.x * cj.x + a1.y * cj.y + a1.z * cj.z + a1.w * cj.w;
    }
#pragma unroll
    for (int o = 16; o; o >>= 1) {
        s0 += __shfl_down_sync(0xffffffffu, s0, o);
        s1 += __shfl_down_sync(0xffffffffu, s1, o);
    }
    if (lane == 0) {
        int r = blockIdx.x * GR + r0;
        float2 r2;
        r2.x = 1.f / (1.f + expf(-(s0 + bz)));
        r2.y = 1.f / (1.f + expf(-(s1 + bz)));
        *(float2*)(g_wt + r) = r2;
    }
}

// ---------------------------------------------------------------------------
// Kernel 2: per batch, strict local minima of wt, left-packed positions.
// 1024 threads, PER=2 -> minimal serial depth in this latency-bound kernel.
// ---------------------------------------------------------------------------
__global__ void k_valleys() {
    __shared__ float sw[TT];
    __shared__ int   wsum[32];

    int b    = blockIdx.x;
    int tid  = threadIdx.x;                // 1024 threads
    int lane = tid & 31;
    int wid  = tid >> 5;                   // 32 warps

    for (int t = tid; t < TT; t += 1024) sw[t] = g_wt[b * TT + t];
    __syncthreads();

    const int PER = TT / 1024;             // 2 consecutive t per thread
    int base = tid * PER;
    unsigned char fl[PER];
    int c = 0;
#pragma unroll
    for (int j = 0; j < PER; j++) {
        int   t   = base + j;
        float wtt = sw[t];
        float bef = (t == 0)      ? 0.f : sw[t - 1];
        float aft = (t == TT - 1) ? 0.f : sw[t + 1];
        bool  v   = (wtt < bef) && (wtt < aft);
        fl[j] = v ? 1 : 0;
        c += v ? 1 : 0;
    }

    int incl = c;
#pragma unroll
    for (int o = 1; o < 32; o <<= 1) {
        int v = __shfl_up_sync(0xffffffffu, incl, o);
        if (lane >= o) incl += v;
    }
    if (lane == 31) wsum[wid] = incl;
    __syncthreads();
    if (tid == 0) {
        int run = 0;
#pragma unroll
        for (int j = 0; j < 32; j++) { int t = wsum[j]; wsum[j] = run; run += t; }
        g_nv[b] = run;
    }
    __syncthreads();

    int pos = wsum[wid] + incl - c;
#pragma unroll
    for (int j = 0; j < PER; j++) {
        if (fl[j]) g_vlist[b * TT + (pos++)] = base + j;
    }
}

// ---------------------------------------------------------------------------
// Kernel 3: streaming segment pooling; SPB consecutive segments per block,
// each x row read once, 2-row overlap carried in registers (ascending sum
// order preserved). Streaming stores keep x resident in L2. Also writes the
// new_mask row slice.
// ---------------------------------------------------------------------------
__global__ void k_pool(const float* __restrict__ x,
                       const int* __restrict__ seq_len,
                       float* __restrict__ out,
                       int write_mask) {
    int b   = blockIdx.y;
    int j   = blockIdx.x;
    int tid = threadIdx.x;                 // 128
    int k = g_nv[b];
    int n = k + 1;
    int i0 = j * SPB;

    float4 z4 = make_float4(0.f, 0.f, 0.f, 0.f);
    for (int i = max(i0, n); i < i0 + SPB; i++)
        __stcs((float4*)(out + ((size_t)b * TT + i) * FF) + tid, z4);

    if (i0 < n) {
        int iEnd = min(i0 + SPB, n);
        const float4* xb = (const float4*)(x + (size_t)b * TT * FF);
        const float*  wb = g_wt + b * TT;
        const int*    vb = g_vlist + b * TT;

        float4 carry = z4;
        float  dcarry = 0.f;
        bool   have = false;

        for (int i = i0; i < iEnd; i++) {
            int S = (i == 0) ? 0 : vb[i - 1];
            int E = (i < k) ? min(vb[i] + 2, TT) : TT;

            float4 acc;
            float  den;
            int t;
            if (have) { acc = carry; den = dcarry; t = S + 2; }
            else      { acc = z4;    den = 0.f;    t = S;     }

            int bodyEnd = E - 2;
#pragma unroll 2
            for (; t < bodyEnd; t++) {
                float  wv = wb[t];
                float4 xv = xb[(size_t)t * (FF / 4) + tid];
                acc.x += wv * xv.x;  acc.y += wv * xv.y;
                acc.z += wv * xv.z;  acc.w += wv * xv.w;
                den += wv;
            }
            float4 c2 = z4;
            float  d2 = 0.f;
            for (; t < E; t++) {
                float  wv = wb[t];
                float4 xv = xb[(size_t)t * (FF / 4) + tid];
                acc.x += wv * xv.x;  acc.y += wv * xv.y;
                acc.z += wv * xv.z;  acc.w += wv * xv.w;
                den += wv;
                c2.x += wv * xv.x;  c2.y += wv * xv.y;
                c2.z += wv * xv.z;  c2.w += wv * xv.w;
                d2 += wv;
            }
            carry = c2; dcarry = d2; have = true;

            float inv = 1.f / fmaxf(den, 1e-6f);
            float4 r;
            r.x = acc.x * inv;  r.y = acc.y * inv;
            r.z = acc.z * inv;  r.w = acc.w * inv;
            __stcs((float4*)(out + ((size_t)b * TT + i) * FF) + tid, r);
        }
    }

    if (write_mask && tid < SPB) {
        int i = i0 + tid;
        int mc = 0;
#pragma unroll
        for (int bb = 0; bb < BB; bb++) {
            int c = g_nv[bb] + 1;
            if (c > mc) mc = c;
        }
        int len  = min(seq_len[b], TT);
        int len0 = min(seq_len[0], TT);
        int nl   = (int)((float)len / (float)len0 * (float)mc);
        float* m = out + (size_t)BB * TT * FF;
        __stcs(&m[(size_t)b * TT + i], (i < nl) ? 1.f : 0.f);
    }
}

// ---------------------------------------------------------------------------
extern "C" void kernel_launch(void* const* d_in, const int* in_sizes, int n_in,
                              void* d_out, int out_size) {
    const float* x    = (const float*)d_in[0];   // [B,T,F] f32
    const float* w    = (const float*)d_in[1];   // [F,1]  f32
    const float* bias = (const float*)d_in[2];   // [1]    f32
    const int*   seq  = (const int*)d_in[3];     // [B]    i32
    float* out = (float*)d_out;

    int write_mask = (out_size >= BB * TT * FF + BB * TT) ? 1 : 0;

    k_gate<<<(BB * TT) / GR, 256>>>(x, w, bias);   // 2048 blocks, TMA
    k_valleys<<<BB, 1024>>>();
    dim3 grid(TT / SPB, BB);                       // 256 x 16 blocks
    k_pool<<<grid, 128>>>(x, seq, out, write_mask);
}

// round 17
// speedup vs baseline: 1.2464x; 1.0471x over previous
#include <cuda_runtime.h>
#include <cstdint>

#define BB 16
#define TT 2048
#define FF 512
#define SPB 8      // segments per k_pool block
#define GR 16      // rows per k_gate block (32KB smem)

// Scratch (allocation-free rule: device globals)
__device__ float g_wt[BB * TT];      // gate weights
__device__ int   g_vlist[BB * TT];   // packed valley positions per batch
__device__ int   g_nv[BB];           // number of valleys k per batch

__device__ __forceinline__ uint32_t smem_u32(const void* p) {
    uint32_t a;
    asm("{ .reg .u64 t; cvta.to.shared.u64 t, %1; cvt.u32.u64 %0, t; }"
        : "=r"(a) : "l"(p));
    return a;
}

// ---------------------------------------------------------------------------
// Kernel 1 (champion, verbatim): wt = sigmoid(x·w + b). One-shot 32KB TMA
// into smem; each warp dots 2 rows from smem against register-held w.
// ---------------------------------------------------------------------------
__global__ void k_gate(const float* __restrict__ x,
                       const float* __restrict__ w,
                       const float* __restrict__ bias) {
    __shared__ alignas(16) float4 sx[GR * FF / 4];          // 32 KB
    __shared__ alignas(8)  unsigned long long mbar;

    int tid  = threadIdx.x;                                  // 256
    int lane = tid & 31;
    int wid  = tid >> 5;                                     // 8 warps

    const float4* wr = (const float4*)w;
    float4 c0 = wr[lane];
    float4 c1 = wr[lane + 32];
    float4 c2 = wr[lane + 64];
    float4 c3 = wr[lane + 96];
    float  bz = bias[0];

    uint32_t mb = smem_u32(&mbar);
    uint32_t ds = smem_u32(sx);
    const int BYTES = GR * FF * 4;                           // 32768

    if (tid == 0) {
        asm volatile("mbarrier.init.shared.b64 [%0], 1;" :: "r"(mb) : "memory");
    }
    __syncthreads();
    if (tid == 0) {
        const char* src = (const char*)x + (size_t)blockIdx.x * BYTES;
        asm volatile("mbarrier.arrive.expect_tx.shared.b64 _, [%0], %1;"
                     :: "r"(mb), "r"(BYTES) : "memory");
        asm volatile("cp.async.bulk.shared::cta.global.mbarrier::complete_tx::bytes "
                     "[%0], [%1], %2, [%3];"
                     :: "r"(ds), "l"(src), "r"(BYTES), "r"(mb) : "memory");
    }

    {
        uint32_t done;
        asm volatile(
            "{\n\t.reg .pred p;\n\t"
            "mbarrier.try_wait.parity.acquire.cta.shared::cta.b64 p, [%1], 0;\n\t"
            "selp.b32 %0, 1, 0, p;\n\t}"
            : "=r"(done) : "r"(mb) : "memory");
        if (!done) {
            asm volatile(
                "{\n\t.reg .pred P1;\n"
                "W%=:\n\t"
                "mbarrier.try_wait.parity.acquire.cta.shared::cta.b64 P1, [%0], 0, 0x989680;\n\t"
                "@P1 bra.uni D%=;\n\t"
                "bra.uni W%=;\n"
                "D%=:\n\t}"
                :: "r"(mb) : "memory");
        }
    }

    int r0 = wid * 2;
    const float4* row0 = sx + r0 * (FF / 4);
    const float4* row1 = row0 + (FF / 4);

    float s0 = 0.f, s1 = 0.f;
#pragma unroll
    for (int j = 0; j < 4; j++) {
        float4 cj = (j == 0) ? c0 : (j == 1) ? c1 : (j == 2) ? c2 : c3;
        float4 a0 = row0[lane + 32 * j];
        float4 a1 = row1[lane + 32 * j];
        s0 += a0.x * cj.x + a0.y * cj.y + a0.z * cj.z + a0.w * cj.w;
        s1 += a1.x * cj.x + a1.y * cj.y + a1.z * cj.z + a1.w * cj.w;
    }
#pragma unroll
    for (int o = 16; o; o >>= 1) {
        s0 += __shfl_down_sync(0xffffffffu, s0, o);
        s1 += __shfl_down_sync(0xffffffffu, s1, o);
    }
    if (lane == 0) {
        int r = blockIdx.x * GR + r0;
        float2 r2;
        r2.x = 1.f / (1.f + expf(-(s0 + bz)));
        r2.y = 1.f / (1.f + expf(-(s1 + bz)));
        *(float2*)(g_wt + r) = r2;
    }
}

// ---------------------------------------------------------------------------
// Kernel 2 (champion + PDL): per batch, strict local minima, left-packed.
// Launched programmatically; grid-dependency sync before reading g_wt.
// ---------------------------------------------------------------------------
__global__ void k_valleys() {
    __shared__ float sw[TT];
    __shared__ int   wsum[32];

    int b    = blockIdx.x;
    int tid  = threadIdx.x;                // 1024 threads
    int lane = tid & 31;
    int wid  = tid >> 5;                   // 32 warps

    cudaGridDependencySynchronize();       // wait for k_gate's g_wt (PDL)

    for (int t = tid; t < TT; t += 1024) sw[t] = g_wt[b * TT + t];
    __syncthreads();

    const int PER = TT / 1024;             // 2
    int base = tid * PER;
    unsigned char fl[PER];
    int c = 0;
#pragma unroll
    for (int j = 0; j < PER; j++) {
        int   t   = base + j;
        float wtt = sw[t];
        float bef = (t == 0)      ? 0.f : sw[t - 1];
        float aft = (t == TT - 1) ? 0.f : sw[t + 1];
        bool  v   = (wtt < bef) && (wtt < aft);
        fl[j] = v ? 1 : 0;
        c += v ? 1 : 0;
    }

    int incl = c;
#pragma unroll
    for (int o = 1; o < 32; o <<= 1) {
        int v = __shfl_up_sync(0xffffffffu, incl, o);
        if (lane >= o) incl += v;
    }
    if (lane == 31) wsum[wid] = incl;
    __syncthreads();
    if (tid == 0) {
        int run = 0;
#pragma unroll
        for (int j = 0; j < 32; j++) { int t = wsum[j]; wsum[j] = run; run += t; }
        g_nv[b] = run;
    }
    __syncthreads();

    int pos = wsum[wid] + incl - c;
#pragma unroll
    for (int j = 0; j < PER; j++) {
        if (fl[j]) g_vlist[b * TT + (pos++)] = base + j;
    }
}

// ---------------------------------------------------------------------------
// Kernel 3 (champion + PDL): streaming segment pooling; SPB segments per
// block, each x row read once, 2-row overlap carried in registers. Streaming
// stores keep x resident in L2. Mask slice included. Grid-dependency sync
// before reading g_nv/g_vlist/g_wt.
// ---------------------------------------------------------------------------
__global__ void k_pool(const float* __restrict__ x,
                       const int* __restrict__ seq_len,
                       float* __restrict__ out,
                       int write_mask) {
    int b   = blockIdx.y;
    int j   = blockIdx.x;
    int tid = threadIdx.x;                 // 128
    int i0 = j * SPB;

    cudaGridDependencySynchronize();       // wait for k_valleys (PDL)

    int k = g_nv[b];
    int n = k + 1;

    float4 z4 = make_float4(0.f, 0.f, 0.f, 0.f);
    for (int i = max(i0, n); i < i0 + SPB; i++)
        __stcs((float4*)(out + ((size_t)b * TT + i) * FF) + tid, z4);

    if (i0 < n) {
        int iEnd = min(i0 + SPB, n);
        const float4* xb = (const float4*)(x + (size_t)b * TT * FF);
        const float*  wb = g_wt + b * TT;
        const int*    vb = g_vlist + b * TT;

        float4 carry = z4;
        float  dcarry = 0.f;
        bool   have = false;

        for (int i = i0; i < iEnd; i++) {
            int S = (i == 0) ? 0 : vb[i - 1];
            int E = (i < k) ? min(vb[i] + 2, TT) : TT;

            float4 acc;
            float  den;
            int t;
            if (have) { acc = carry; den = dcarry; t = S + 2; }
            else      { acc = z4;    den = 0.f;    t = S;     }

            int bodyEnd = E - 2;
#pragma unroll 2
            for (; t < bodyEnd; t++) {
                float  wv = wb[t];
                float4 xv = xb[(size_t)t * (FF / 4) + tid];
                acc.x += wv * xv.x;  acc.y += wv * xv.y;
                acc.z += wv * xv.z;  acc.w += wv * xv.w;
                den += wv;
            }
            float4 c2 = z4;
            float  d2 = 0.f;
            for (; t < E; t++) {
                float  wv = wb[t];
                float4 xv = xb[(size_t)t * (FF / 4) + tid];
                acc.x += wv * xv.x;  acc.y += wv * xv.y;
                acc.z += wv * xv.z;  acc.w += wv * xv.w;
                den += wv;
                c2.x += wv * xv.x;  c2.y += wv * xv.y;
                c2.z += wv * xv.z;  c2.w += wv * xv.w;
                d2 += wv;
            }
            carry = c2; dcarry = d2; have = true;

            float inv = 1.f / fmaxf(den, 1e-6f);
            float4 r;
            r.x = acc.x * inv;  r.y = acc.y * inv;
            r.z = acc.z * inv;  r.w = acc.w * inv;
            __stcs((float4*)(out + ((size_t)b * TT + i) * FF) + tid, r);
        }
    }

    if (write_mask && tid < SPB) {
        int i = i0 + tid;
        int mc = 0;
#pragma unroll
        for (int bb = 0; bb < BB; bb++) {
            int c = g_nv[bb] + 1;
            if (c > mc) mc = c;
        }
        int len  = min(seq_len[b], TT);
        int len0 = min(seq_len[0], TT);
        int nl   = (int)((float)len / (float)len0 * (float)mc);
        float* m = out + (size_t)BB * TT * FF;
        __stcs(&m[(size_t)b * TT + i], (i < nl) ? 1.f : 0.f);
    }
}

// ---------------------------------------------------------------------------
extern "C" void kernel_launch(void* const* d_in, const int* in_sizes, int n_in,
                              void* d_out, int out_size) {
    const float* x    = (const float*)d_in[0];   // [B,T,F] f32
    const float* w    = (const float*)d_in[1];   // [F,1]  f32
    const float* bias = (const float*)d_in[2];   // [1]    f32
    const int*   seq  = (const int*)d_in[3];     // [B]    i32
    float* out = (float*)d_out;

    int write_mask = (out_size >= BB * TT * FF + BB * TT) ? 1 : 0;

    k_gate<<<(BB * TT) / GR, 256>>>(x, w, bias);   // 2048 blocks, TMA

    // PDL launches: successor placed during predecessor's tail wave; the
    // in-kernel cudaGridDependencySynchronize provides the ordering.
    cudaLaunchAttribute attr[1];
    attr[0].id = cudaLaunchAttributeProgrammaticStreamSerialization;
    attr[0].val.programmaticStreamSerializationAllowed = 1;

    cudaLaunchConfig_t cfgV = {};
    cfgV.gridDim  = dim3(BB, 1, 1);
    cfgV.blockDim = dim3(1024, 1, 1);
    cfgV.attrs    = attr;
    cfgV.numAttrs = 1;
    if (cudaLaunchKernelEx(&cfgV, k_valleys) != cudaSuccess)
        k_valleys<<<BB, 1024>>>();                 // fallback (sync is no-op)

    cudaLaunchConfig_t cfgP = {};
    cfgP.gridDim  = dim3(TT / SPB, BB, 1);         // 256 x 16 blocks
    cfgP.blockDim = dim3(128, 1, 1);
    cfgP.attrs    = attr;
    cfgP.numAttrs = 1;
    if (cudaLaunchKernelEx(&cfgP, k_pool, x, seq, out, write_mask) != cudaSuccess) {
        dim3 grid(TT / SPB, BB);
        k_pool<<<grid, 128>>>(x, seq, out, write_mask);
    }
}